// round 11
// baseline (speedup 1.0000x reference)
#include <cuda_runtime.h>
#include <cstdint>

#define Bq   128
#define Sq   512
#define Eq   256
#define HDq  256
#define NTq  9

// ---- scratch (device globals; no allocation allowed) ----
__device__ float  g_h[Bq][Sq][2*HDq];        // [b][s][dir*256+j]
__device__ float  g_em[Bq][Sq][NTq];         // emissions
__device__ int    g_len[Bq];
__device__ unsigned g_cnt[2][4];             // per-(dir,batch-group) step counters
__device__ float  g_llh[Bq];

typedef unsigned long long ull;

__device__ __forceinline__ ull pk2(float x, float y){
    ull r; asm("mov.b64 %0, {%1, %2};" : "=l"(r) : "f"(x), "f"(y)); return r;
}
__device__ __forceinline__ float2 up2(ull v){
    float2 r; asm("mov.b64 {%0, %1}, %2;" : "=f"(r.x), "=f"(r.y) : "l"(v)); return r;
}
__device__ __forceinline__ ull fma2(ull a, ull b, ull c){
    ull d; asm("fma.rn.f32x2 %0, %1, %2, %3;" : "=l"(d) : "l"(a), "l"(b), "l"(c)); return d;
}
__device__ __forceinline__ float tanhfast(float x){
    float y; asm("tanh.approx.f32 %0, %1;" : "=f"(y) : "f"(x)); return y;
}
__device__ __forceinline__ float sigf(float x){ return 0.5f*tanhfast(0.5f*x) + 0.5f; }

__device__ __forceinline__ uint32_t smem_u32(const void* p){
    uint32_t a;
    asm("{ .reg .u64 t; cvta.to.shared.u64 t, %1; cvt.u32.u64 %0, t; }"
        : "=r"(a) : "l"(p));
    return a;
}
__device__ __forceinline__ void cpasync16(uint32_t dst, const void* src){
    asm volatile("cp.async.ca.shared.global [%0], [%1], 16;" :: "r"(dst), "l"(src));
}

// ---------------------------------------------------------------------------
// prep: reset barrier counters, detect mask dtype, compute per-row lengths
// ---------------------------------------------------------------------------
__global__ void k_prep(const void* __restrict__ mask){
    const int b = threadIdx.x;
    if (b < 8) g_cnt[b >> 2][b & 3] = 0u;
    const unsigned char* m8 = (const unsigned char*)mask;
    const bool u8 = (m8[1] != 0);
    const int* m32 = (const int*)mask;
    int cnt = 0;
    for (int s = 0; s < Sq; s++)
        cnt += u8 ? (m8[b*Sq + s] != 0) : (m32[b*Sq + s] != 0);
    g_len[b] = cnt;
}

// no-ops: put ncu's profiled slot (4th launch) on k_fused
__global__ void k_nop(){}

// ---------------------------------------------------------------------------
// inner GEMM fragment, 2 rows x 1 quad per thread:
// A-chain = row0's quad accum, B-chain = row1's. Weight loads shared by rows.
// ---------------------------------------------------------------------------
__device__ __forceinline__ void gemm2(
    const float* __restrict__ arow0, const float* __restrict__ arow1,
    const float* __restrict__ W, int col, int kbeg, int kend,
    ull& A0, ull& A1, ull& B0, ull& B1)
{
    #pragma unroll 4
    for (int k = kbeg; k < kend; k += 4){
        float4 a0 = *reinterpret_cast<const float4*>(arow0 + k);
        float4 a1 = *reinterpret_cast<const float4*>(arow1 + k);
        {
            ulonglong2 w0 = *reinterpret_cast<const ulonglong2*>(W + (k+0)*68 + col);
            ull u = pk2(a0.x, a0.x), v = pk2(a1.x, a1.x);
            A0 = fma2(u, w0.x, A0); A1 = fma2(u, w0.y, A1);
            B0 = fma2(v, w0.x, B0); B1 = fma2(v, w0.y, B1);
        }
        {
            ulonglong2 w1 = *reinterpret_cast<const ulonglong2*>(W + (k+1)*68 + col);
            ull u = pk2(a0.y, a0.y), v = pk2(a1.y, a1.y);
            A0 = fma2(u, w1.x, A0); A1 = fma2(u, w1.y, A1);
            B0 = fma2(v, w1.x, B0); B1 = fma2(v, w1.y, B1);
        }
        {
            ulonglong2 w2 = *reinterpret_cast<const ulonglong2*>(W + (k+2)*68 + col);
            ull u = pk2(a0.z, a0.z), v = pk2(a1.z, a1.z);
            A0 = fma2(u, w2.x, A0); A1 = fma2(u, w2.y, A1);
            B0 = fma2(v, w2.x, B0); B1 = fma2(v, w2.y, B1);
        }
        {
            ulonglong2 w3 = *reinterpret_cast<const ulonglong2*>(W + (k+3)*68 + col);
            ull u = pk2(a0.w, a0.w), v = pk2(a1.w, a1.w);
            A0 = fma2(u, w3.x, A0); A1 = fma2(u, w3.y, A1);
            B0 = fma2(v, w3.x, B0); B1 = fma2(v, w3.y, B1);
        }
    }
}

// ---------------------------------------------------------------------------
// fused BiLSTM (input projection + recurrence), persistent:
// 128 CTAs = 2 dirs x 4 batch-groups(32 rows) x 16 gate-slices(64 cols)
// thread tile: 2 rows x 1 i/f/g/o quad (weight LDS shared across rows)
// per step: x-GEMM (emb . w_ih^T) then h-GEMM (h . w_hh^T), gates, exchange.
// permutation: p = j*4 + q (q in {i,f,g,o}), source row r0 = q*256 + j
// ---------------------------------------------------------------------------
__global__ void __launch_bounds__(256,1) k_fused(
    const int*   __restrict__ X,     const float* __restrict__ emb,
    const float* __restrict__ wihf,  const float* __restrict__ whhf,
    const float* __restrict__ bif,   const float* __restrict__ bhf,
    const float* __restrict__ wihb,  const float* __restrict__ whhb,
    const float* __restrict__ bib,   const float* __restrict__ bhb)
{
    extern __shared__ float sm[];
    float* Wih = sm;                  // [256][68]
    float* Whh = sm + 256*68;         // [256][68]
    float* Hs  = sm + 2*256*68;       // [32][260]
    float* E   = Hs + 32*260;         // [32][260]
    const int cta = blockIdx.x;
    const int dir = cta >> 6;
    const int bg  = (cta >> 4) & 3;
    const int sl  = cta & 15;
    const int t   = threadIdx.x;
    const float* __restrict__ wih = dir ? wihb : wihf;
    const float* __restrict__ whh = dir ? whhb : whhf;
    const float* __restrict__ bi  = dir ? bib  : bif;
    const float* __restrict__ bh  = dir ? bhb  : bhf;
    unsigned* cntp = &g_cnt[dir][bg];
    const uint32_t hs_u32 = smem_u32(Hs);
    const uint32_t e_u32  = smem_u32(E);

    // ---- load + transpose both weight slices (64 permuted cols each) ----
    {
        int c  = t & 63;
        int kq = t >> 6;
        int p  = sl*64 + c;
        int r0 = (p & 3)*HDq + (p >> 2);
        const float4* sih = reinterpret_cast<const float4*>(wih + (size_t)r0*Eq)  + kq*16;
        const float4* shh = reinterpret_cast<const float4*>(whh + (size_t)r0*HDq) + kq*16;
        #pragma unroll
        for (int i = 0; i < 16; i++){
            float4 v = sih[i];
            int k0 = kq*64 + i*4;
            Wih[(k0+0)*68 + c] = v.x; Wih[(k0+1)*68 + c] = v.y;
            Wih[(k0+2)*68 + c] = v.z; Wih[(k0+3)*68 + c] = v.w;
            v = shh[i];
            Whh[(k0+0)*68 + c] = v.x; Whh[(k0+1)*68 + c] = v.y;
            Whh[(k0+2)*68 + c] = v.z; Whh[(k0+3)*68 + c] = v.w;
        }
    }

    // ---- thread tile: warp = 8 rows x 32 cols; thread = 2 rows x 1 quad ----
    const int warp = t >> 5, lane = t & 31;
    const int wr = warp >> 1, wc = warp & 1;
    const int r4 = lane >> 3, c8 = lane & 7;
    const int row0 = wr*8 + r4*2;          // rows row0, row0+1
    const int col  = wc*32 + c8*4;         // quad cols (4 permuted gates)
    const int bgl0 = bg*32 + row0;
    const int bgl1 = bgl0 + 1;
    const int j    = sl*16 + wc*8 + c8;    // h element index
    const float* erow0 = E  + row0*260;
    const float* erow1 = E  + (row0+1)*260;
    const float* hrow0 = Hs + row0*260;
    const float* hrow1 = Hs + (row0+1)*260;

    // ---- bias seeds (packed f32x2, same quad both rows) ----
    ull bQ0, bQ1;
    {
        int p0 = sl*64 + col;
        auto bv = [&](int p){ int r = (p & 3)*HDq + (p >> 2); return bi[r] + bh[r]; };
        bQ0 = pk2(bv(p0+0), bv(p0+1)); bQ1 = pk2(bv(p0+2), bv(p0+3));
    }

    // ---- preload E (emb tile for step 0) ----
    {
        int tt0 = dir ? (Sq-1) : 0;
        #pragma unroll
        for (int i = 0; i < 8; i++){
            int idx = t + i*256, r = idx >> 6, q = idx & 63;
            int tok = X[(bg*32 + r)*Sq + tt0];
            cpasync16(e_u32 + (uint32_t)((r*260 + q*4)*4),
                      emb + (size_t)tok*Eq + q*4);
        }
        asm volatile("cp.async.commit_group;" ::: "memory");
        asm volatile("cp.async.wait_group 0;" ::: "memory");
    }
    __syncthreads();

    float cA = 0.f, cB = 0.f;

    for (int step = 0; step < Sq; step++){
        const int tt = dir ? (Sq-1-step) : step;

        ull aA0 = bQ0, aA1 = bQ1, aB0 = bQ0, aB1 = bQ1;

        // x-GEMM first half (independent of other CTAs)
        gemm2(erow0, erow1, Wih, col, 0, 128, aA0, aA1, aB0, aB1);

        if (step){
            // wait for all 16 CTAs' h(t-1) stores (acquire), then gather
            if (t == 0){
                const unsigned target = 16u*(unsigned)step;
                unsigned v;
                do {
                    asm volatile("ld.acquire.gpu.global.u32 %0, [%1];"
                                 : "=r"(v) : "l"(cntp) : "memory");
                } while (v < target);
            }
            __syncthreads();
            const int ttp = dir ? (Sq - step) : (step - 1);
            #pragma unroll
            for (int i = 0; i < 8; i++){
                int idx = t + i*256, r = idx >> 6, q = idx & 63;
                cpasync16(hs_u32 + (uint32_t)((r*260 + q*4)*4),
                          &g_h[bg*32 + r][ttp][dir*HDq + q*4]);
            }
            asm volatile("cp.async.commit_group;" ::: "memory");
        }

        // x-GEMM second half (hides the gather)
        gemm2(erow0, erow1, Wih, col, 128, 256, aA0, aA1, aB0, aB1);

        if (step){
            asm volatile("cp.async.wait_group 0;" ::: "memory");   // gather done
        }
        __syncthreads();   // Hs visible; all threads finished reading E

        // prefetch emb(t+1) into E (hidden under h-GEMM + gates)
        if (step + 1 < Sq){
            const int tn = dir ? (Sq-2-step) : (step+1);
            #pragma unroll
            for (int i = 0; i < 8; i++){
                int idx = t + i*256, r = idx >> 6, q = idx & 63;
                int tok = X[(bg*32 + r)*Sq + tn];
                cpasync16(e_u32 + (uint32_t)((r*260 + q*4)*4),
                          emb + (size_t)tok*Eq + q*4);
            }
            asm volatile("cp.async.commit_group;" ::: "memory");
        }

        if (step){
            gemm2(hrow0, hrow1, Whh, col, 0, 256, aA0, aA1, aB0, aB1);
        }

        // gates: (i,f) in *0, (g,o) in *1; A = row0, B = row1
        float2 gA0 = up2(aA0), gA1 = up2(aA1);
        float2 gB0 = up2(aB0), gB1 = up2(aB1);
        cA = sigf(gA0.y)*cA + sigf(gA0.x)*tanhfast(gA1.x);
        float hA = sigf(gA1.y)*tanhfast(cA);
        cB = sigf(gB0.y)*cB + sigf(gB0.x)*tanhfast(gB1.x);
        float hB = sigf(gB1.y)*tanhfast(cB);

        g_h[bgl0][tt][dir*HDq + j] = hA;
        g_h[bgl1][tt][dir*HDq + j] = hB;

        if (step + 1 < Sq){
            __syncthreads();                       // all h stores issued
            if (t == 0){
                asm volatile("red.release.gpu.global.add.u32 [%0], %1;"
                             :: "l"(cntp), "r"(1u) : "memory");
            }
            asm volatile("cp.async.wait_group 0;" ::: "memory");   // E ready
            __syncthreads();
        }
    }
}

// ---------------------------------------------------------------------------
// emissions
// ---------------------------------------------------------------------------
__global__ void __launch_bounds__(256) k_emis(
    const float* __restrict__ lin_w, const float* __restrict__ lin_b)
{
    __shared__ float ws[NTq*512];
    const int t = threadIdx.x;
    for (int i = t; i < NTq*512; i += 256) ws[i] = lin_w[i];
    __syncthreads();
    const int warp = t >> 5, lane = t & 31;
    const int pos = blockIdx.x*8 + warp;
    const int b = pos >> 9, s = pos & 511;
    const float* orow = &g_h[b][s][0];
    float acc[NTq];
    #pragma unroll
    for (int k = 0; k < NTq; k++) acc[k] = 0.f;
    #pragma unroll 4
    for (int it = 0; it < 16; it++){
        float ov = orow[it*32 + lane];
        #pragma unroll
        for (int k = 0; k < NTq; k++) acc[k] += ov * ws[k*512 + it*32 + lane];
    }
    #pragma unroll
    for (int k = 0; k < NTq; k++){
        #pragma unroll
        for (int off = 16; off > 0; off >>= 1)
            acc[k] += __shfl_xor_sync(0xffffffffu, acc[k], off);
    }
    if (lane < NTq){
        float v = 0.f;
        #pragma unroll
        for (int k = 0; k < NTq; k++) if (lane == k) v = acc[k];
        g_em[b][s][lane] = v + lin_b[lane];
    }
}

// ---------------------------------------------------------------------------
// CRF log-likelihood: one warp per batch row
// ---------------------------------------------------------------------------
__global__ void __launch_bounds__(1024) k_crf(
    const int*   __restrict__ y,
    const float* __restrict__ st, const float* __restrict__ en,
    const float* __restrict__ tr)
{
    const int t = threadIdx.x;
    const int warp = t >> 5, lane = t & 31;
    const int b = blockIdx.x*32 + warp;
    const int L = g_len[b];
    const int* yr = y + b*Sq;
    const float* emr = &g_em[b][0][0];
    const int lc = (lane < NTq) ? lane : (NTq-1);

    float num = 0.f;
    for (int tt = lane; tt < L; tt += 32){
        int yt = yr[tt];
        num += emr[tt*NTq + yt];
        if (tt > 0) num += tr[yr[tt-1]*NTq + yt];
    }
    #pragma unroll
    for (int off = 16; off > 0; off >>= 1)
        num += __shfl_xor_sync(0xffffffffu, num, off);

    float trv[NTq];
    #pragma unroll
    for (int i = 0; i < NTq; i++) trv[i] = tr[i*NTq + lc];
    float alpha = st[lc] + emr[lc];
    for (int tt = 1; tt < L; tt++){
        float vals[NTq]; float m = -3.0e38f;
        #pragma unroll
        for (int i = 0; i < NTq; i++){
            float ai = __shfl_sync(0xffffffffu, alpha, i);
            vals[i] = ai + trv[i];
            m = fmaxf(m, vals[i]);
        }
        float ssum = 0.f;
        #pragma unroll
        for (int i = 0; i < NTq; i++) ssum += __expf(vals[i]-m);
        alpha = m + __logf(ssum) + emr[tt*NTq + lc];
    }
    float v = (lane < NTq) ? (alpha + en[lane]) : -3.0e38f;
    float m = v;
    #pragma unroll
    for (int off = 16; off > 0; off >>= 1)
        m = fmaxf(m, __shfl_xor_sync(0xffffffffu, m, off));
    float e = __expf(v - m);
    #pragma unroll
    for (int off = 16; off > 0; off >>= 1)
        e += __shfl_xor_sync(0xffffffffu, e, off);
    float den = m + __logf(e);
    if (lane == 0)
        g_llh[b] = num + st[yr[0]] + en[yr[L-1]] - den;
}

__global__ void k_finsum(float* __restrict__ out){
    const int lane = threadIdx.x;
    float s1 = g_llh[lane] + g_llh[lane+32] + g_llh[lane+64] + g_llh[lane+96];
    #pragma unroll
    for (int off = 16; off > 0; off >>= 1)
        s1 += __shfl_xor_sync(0xffffffffu, s1, off);
    if (lane == 0) out[0] = s1;
}

// ---------------------------------------------------------------------------
extern "C" void kernel_launch(void* const* d_in, const int* in_sizes, int n_in,
                              void* d_out, int out_size)
{
    const int*   X      = (const int*)  d_in[0];
    const int*   y      = (const int*)  d_in[1];
    const void*  mask   =               d_in[2];
    const float* emb    = (const float*)d_in[3];
    const float* w_ih_f = (const float*)d_in[4];
    const float* w_hh_f = (const float*)d_in[5];
    const float* b_ih_f = (const float*)d_in[6];
    const float* b_hh_f = (const float*)d_in[7];
    const float* w_ih_b = (const float*)d_in[8];
    const float* w_hh_b = (const float*)d_in[9];
    const float* b_ih_b = (const float*)d_in[10];
    const float* b_hh_b = (const float*)d_in[11];
    const float* lin_w  = (const float*)d_in[12];
    const float* lin_b  = (const float*)d_in[13];
    const float* st     = (const float*)d_in[14];
    const float* en     = (const float*)d_in[15];
    const float* tr     = (const float*)d_in[16];

    const int SMEM3 = (2*256*68 + 2*32*260) * 4;   // 205,824 B
    cudaFuncSetAttribute(k_fused, cudaFuncAttributeMaxDynamicSharedMemorySize, SMEM3);

    k_prep<<<1, 128>>>(mask);
    k_nop<<<1, 32>>>();   // shift ncu's profiled slot ...
    k_nop<<<1, 32>>>();   // ... onto k_fused (4th launch)
    k_fused<<<128, 256, SMEM3>>>(X, emb,
                                 w_ih_f, w_hh_f, b_ih_f, b_hh_f,
                                 w_ih_b, w_hh_b, b_ih_b, b_hh_b);
    k_emis<<<8192, 256>>>(lin_w, lin_b);
    k_crf<<<4, 1024>>>(y, st, en, tr);
    k_finsum<<<1, 32>>>((float*)d_out);
}

// round 12
// speedup vs baseline: 1.0783x; 1.0783x over previous
#include <cuda_runtime.h>
#include <cstdint>

#define Bq   128
#define Sq   512
#define Eq   256
#define HDq  256
#define NTq  9

// ---- scratch (device globals; no allocation allowed) ----
__device__ float  g_h[Bq][Sq][2*HDq];        // [b][s][dir*256+j]
__device__ float  g_em[Bq][Sq][NTq];         // emissions
__device__ int    g_len[Bq];
__device__ unsigned g_cnt[2][4];             // per-(dir,batch-group) step counters
__device__ float  g_llh[Bq];

typedef unsigned long long ull;

__device__ __forceinline__ ull pk2(float x, float y){
    ull r; asm("mov.b64 %0, {%1, %2};" : "=l"(r) : "f"(x), "f"(y)); return r;
}
__device__ __forceinline__ float2 up2(ull v){
    float2 r; asm("mov.b64 {%0, %1}, %2;" : "=f"(r.x), "=f"(r.y) : "l"(v)); return r;
}
__device__ __forceinline__ ull fma2(ull a, ull b, ull c){
    ull d; asm("fma.rn.f32x2 %0, %1, %2, %3;" : "=l"(d) : "l"(a), "l"(b), "l"(c)); return d;
}
__device__ __forceinline__ float tanhfast(float x){
    float y; asm("tanh.approx.f32 %0, %1;" : "=f"(y) : "f"(x)); return y;
}
__device__ __forceinline__ float sigf(float x){ return 0.5f*tanhfast(0.5f*x) + 0.5f; }

__device__ __forceinline__ uint32_t smem_u32(const void* p){
    uint32_t a;
    asm("{ .reg .u64 t; cvta.to.shared.u64 t, %1; cvt.u32.u64 %0, t; }"
        : "=r"(a) : "l"(p));
    return a;
}
__device__ __forceinline__ void cpasync16(uint32_t dst, const void* src){
    asm volatile("cp.async.ca.shared.global [%0], [%1], 16;" :: "r"(dst), "l"(src));
}

// ---------------------------------------------------------------------------
// prep: reset barrier counters, detect mask dtype, compute per-row lengths
// ---------------------------------------------------------------------------
__global__ void k_prep(const void* __restrict__ mask){
    const int b = threadIdx.x;
    if (b < 8) g_cnt[b >> 2][b & 3] = 0u;
    const unsigned char* m8 = (const unsigned char*)mask;
    const bool u8 = (m8[1] != 0);
    const int* m32 = (const int*)mask;
    int cnt = 0;
    for (int s = 0; s < Sq; s++)
        cnt += u8 ? (m8[b*Sq + s] != 0) : (m32[b*Sq + s] != 0);
    g_len[b] = cnt;
}

// no-ops: put ncu's profiled slot (4th launch) on k_fused
__global__ void k_nop(){}

// ---------------------------------------------------------------------------
// software-pipelined GEMM fragment: 1 row x 2 quads per thread
// operands for block k+4 are loaded before block k's FMAs execute
// ---------------------------------------------------------------------------
__device__ __forceinline__ void lda4(const float* __restrict__ arow, int k, float4& a){
    a = *reinterpret_cast<const float4*>(arow + k);
}
__device__ __forceinline__ void ldw8(const float* __restrict__ W, int k,
                                     int colA, int colB, ulonglong2* w){
    w[0] = *reinterpret_cast<const ulonglong2*>(W + (k+0)*68 + colA);
    w[1] = *reinterpret_cast<const ulonglong2*>(W + (k+0)*68 + colB);
    w[2] = *reinterpret_cast<const ulonglong2*>(W + (k+1)*68 + colA);
    w[3] = *reinterpret_cast<const ulonglong2*>(W + (k+1)*68 + colB);
    w[4] = *reinterpret_cast<const ulonglong2*>(W + (k+2)*68 + colA);
    w[5] = *reinterpret_cast<const ulonglong2*>(W + (k+2)*68 + colB);
    w[6] = *reinterpret_cast<const ulonglong2*>(W + (k+3)*68 + colA);
    w[7] = *reinterpret_cast<const ulonglong2*>(W + (k+3)*68 + colB);
}
__device__ __forceinline__ void fmab(const float4& a, const ulonglong2* w,
                                     ull& A0, ull& A1, ull& B0, ull& B1){
    ull u;
    u = pk2(a.x, a.x);
    A0 = fma2(u, w[0].x, A0); A1 = fma2(u, w[0].y, A1);
    B0 = fma2(u, w[1].x, B0); B1 = fma2(u, w[1].y, B1);
    u = pk2(a.y, a.y);
    A0 = fma2(u, w[2].x, A0); A1 = fma2(u, w[2].y, A1);
    B0 = fma2(u, w[3].x, B0); B1 = fma2(u, w[3].y, B1);
    u = pk2(a.z, a.z);
    A0 = fma2(u, w[4].x, A0); A1 = fma2(u, w[4].y, A1);
    B0 = fma2(u, w[5].x, B0); B1 = fma2(u, w[5].y, B1);
    u = pk2(a.w, a.w);
    A0 = fma2(u, w[6].x, A0); A1 = fma2(u, w[6].y, A1);
    B0 = fma2(u, w[7].x, B0); B1 = fma2(u, w[7].y, B1);
}

__device__ __forceinline__ void gemm_pl(
    const float* __restrict__ arow, const float* __restrict__ W,
    int colA, int colB, int kbeg, int kend,
    ull& A0, ull& A1, ull& B0, ull& B1)
{
    float4 a0, a1;
    ulonglong2 w0[8], w1[8];
    lda4(arow, kbeg, a0);
    ldw8(W, kbeg, colA, colB, w0);
    #pragma unroll
    for (int k = kbeg; k < kend; k += 8){
        lda4(arow, k+4, a1);
        ldw8(W, k+4, colA, colB, w1);
        fmab(a0, w0, A0, A1, B0, B1);
        if (k + 8 < kend){
            lda4(arow, k+8, a0);
            ldw8(W, k+8, colA, colB, w0);
        }
        fmab(a1, w1, A0, A1, B0, B1);
    }
}

// ---------------------------------------------------------------------------
// fused BiLSTM (input projection + recurrence), persistent:
// 128 CTAs = 2 dirs x 4 batch-groups(32 rows) x 16 gate-slices(64 cols)
// thread tile: 1 row x 2 i/f/g/o quads; software-pipelined operand loads
// per step: x-GEMM (emb . w_ih^T) then h-GEMM (h . w_hh^T), gates, exchange.
// permutation: p = j*4 + q (q in {i,f,g,o}), source row r0 = q*256 + j
// ---------------------------------------------------------------------------
__global__ void __launch_bounds__(256,1) k_fused(
    const int*   __restrict__ X,     const float* __restrict__ emb,
    const float* __restrict__ wihf,  const float* __restrict__ whhf,
    const float* __restrict__ bif,   const float* __restrict__ bhf,
    const float* __restrict__ wihb,  const float* __restrict__ whhb,
    const float* __restrict__ bib,   const float* __restrict__ bhb)
{
    extern __shared__ float sm[];
    float* Wih = sm;                  // [256][68]
    float* Whh = sm + 256*68;         // [256][68]
    float* Hs  = sm + 2*256*68;       // [32][260]
    float* E   = Hs + 32*260;         // [32][260]
    const int cta = blockIdx.x;
    const int dir = cta >> 6;
    const int bg  = (cta >> 4) & 3;
    const int sl  = cta & 15;
    const int t   = threadIdx.x;
    const float* __restrict__ wih = dir ? wihb : wihf;
    const float* __restrict__ whh = dir ? whhb : whhf;
    const float* __restrict__ bi  = dir ? bib  : bif;
    const float* __restrict__ bh  = dir ? bhb  : bhf;
    unsigned* cntp = &g_cnt[dir][bg];
    const uint32_t hs_u32 = smem_u32(Hs);
    const uint32_t e_u32  = smem_u32(E);

    // ---- load + transpose both weight slices (64 permuted cols each) ----
    {
        int c  = t & 63;
        int kq = t >> 6;
        int p  = sl*64 + c;
        int r0 = (p & 3)*HDq + (p >> 2);
        const float4* sih = reinterpret_cast<const float4*>(wih + (size_t)r0*Eq)  + kq*16;
        const float4* shh = reinterpret_cast<const float4*>(whh + (size_t)r0*HDq) + kq*16;
        #pragma unroll
        for (int i = 0; i < 16; i++){
            float4 v = sih[i];
            int k0 = kq*64 + i*4;
            Wih[(k0+0)*68 + c] = v.x; Wih[(k0+1)*68 + c] = v.y;
            Wih[(k0+2)*68 + c] = v.z; Wih[(k0+3)*68 + c] = v.w;
            v = shh[i];
            Whh[(k0+0)*68 + c] = v.x; Whh[(k0+1)*68 + c] = v.y;
            Whh[(k0+2)*68 + c] = v.z; Whh[(k0+3)*68 + c] = v.w;
        }
    }

    // ---- thread tile: warp = (row-half, col-quarter); lane = (row16, colgrp) ----
    const int warp = t >> 5, lane = t & 31;
    const int rh = warp >> 2, cq = warp & 3;
    const int rl = lane >> 1, cg = lane & 1;
    const int row  = rh*16 + rl;          // 0..31
    const int colA = cq*16 + cg*4;        // quad A cols
    const int colB = colA + 8;            // quad B cols
    const int bgl  = bg*32 + row;
    const int jA   = sl*16 + (colA >> 2); // h element index for quad A
    const int jB   = jA + 2;
    const float* erow = E  + row*260;
    const float* hrow = Hs + row*260;

    // ---- bias seeds (packed f32x2) ----
    ull bA0, bA1, bB0, bB1;
    {
        int pA = sl*64 + colA, pB = sl*64 + colB;
        auto bv = [&](int p){ int r = (p & 3)*HDq + (p >> 2); return bi[r] + bh[r]; };
        bA0 = pk2(bv(pA+0), bv(pA+1)); bA1 = pk2(bv(pA+2), bv(pA+3));
        bB0 = pk2(bv(pB+0), bv(pB+1)); bB1 = pk2(bv(pB+2), bv(pB+3));
    }

    // ---- preload E (emb tile for step 0) ----
    {
        int tt0 = dir ? (Sq-1) : 0;
        #pragma unroll
        for (int i = 0; i < 8; i++){
            int idx = t + i*256, r = idx >> 6, q = idx & 63;
            int tok = X[(bg*32 + r)*Sq + tt0];
            cpasync16(e_u32 + (uint32_t)((r*260 + q*4)*4),
                      emb + (size_t)tok*Eq + q*4);
        }
        asm volatile("cp.async.commit_group;" ::: "memory");
        asm volatile("cp.async.wait_group 0;" ::: "memory");
    }
    __syncthreads();

    float cA = 0.f, cB = 0.f;

    for (int step = 0; step < Sq; step++){
        const int tt = dir ? (Sq-1-step) : step;

        ull aA0 = bA0, aA1 = bA1, aB0 = bB0, aB1 = bB1;

        // x-GEMM first half (independent of other CTAs)
        gemm_pl(erow, Wih, colA, colB, 0, 128, aA0, aA1, aB0, aB1);

        if (step){
            // wait for all 16 CTAs' h(t-1) stores (acquire), then gather
            if (t == 0){
                const unsigned target = 16u*(unsigned)step;
                unsigned v;
                do {
                    asm volatile("ld.acquire.gpu.global.u32 %0, [%1];"
                                 : "=r"(v) : "l"(cntp) : "memory");
                } while (v < target);
            }
            __syncthreads();
            const int ttp = dir ? (Sq - step) : (step - 1);
            #pragma unroll
            for (int i = 0; i < 8; i++){
                int idx = t + i*256, r = idx >> 6, q = idx & 63;
                cpasync16(hs_u32 + (uint32_t)((r*260 + q*4)*4),
                          &g_h[bg*32 + r][ttp][dir*HDq + q*4]);
            }
            asm volatile("cp.async.commit_group;" ::: "memory");
        }

        // x-GEMM second half (hides the gather)
        gemm_pl(erow, Wih, colA, colB, 128, 256, aA0, aA1, aB0, aB1);

        if (step){
            asm volatile("cp.async.wait_group 0;" ::: "memory");   // gather done
        }
        __syncthreads();   // Hs visible; all threads finished reading E

        // prefetch emb(t+1) into E (hidden under h-GEMM + gates)
        if (step + 1 < Sq){
            const int tn = dir ? (Sq-2-step) : (step+1);
            #pragma unroll
            for (int i = 0; i < 8; i++){
                int idx = t + i*256, r = idx >> 6, q = idx & 63;
                int tok = X[(bg*32 + r)*Sq + tn];
                cpasync16(e_u32 + (uint32_t)((r*260 + q*4)*4),
                          emb + (size_t)tok*Eq + q*4);
            }
            asm volatile("cp.async.commit_group;" ::: "memory");
        }

        if (step){
            gemm_pl(hrow, Whh, colA, colB, 0, 256, aA0, aA1, aB0, aB1);
        }

        // gates (i,f) in *0, (g,o) in *1, per quad
        float2 gA0 = up2(aA0), gA1 = up2(aA1);
        float2 gB0 = up2(aB0), gB1 = up2(aB1);
        cA = sigf(gA0.y)*cA + sigf(gA0.x)*tanhfast(gA1.x);
        float hA = sigf(gA1.y)*tanhfast(cA);
        cB = sigf(gB0.y)*cB + sigf(gB0.x)*tanhfast(gB1.x);
        float hB = sigf(gB1.y)*tanhfast(cB);

        g_h[bgl][tt][dir*HDq + jA] = hA;
        g_h[bgl][tt][dir*HDq + jB] = hB;

        if (step + 1 < Sq){
            __syncthreads();                       // all h stores issued
            if (t == 0){
                asm volatile("red.release.gpu.global.add.u32 [%0], %1;"
                             :: "l"(cntp), "r"(1u) : "memory");
            }
            asm volatile("cp.async.wait_group 0;" ::: "memory");   // E ready
            __syncthreads();
        }
    }
}

// ---------------------------------------------------------------------------
// emissions
// ---------------------------------------------------------------------------
__global__ void __launch_bounds__(256) k_emis(
    const float* __restrict__ lin_w, const float* __restrict__ lin_b)
{
    __shared__ float ws[NTq*512];
    const int t = threadIdx.x;
    for (int i = t; i < NTq*512; i += 256) ws[i] = lin_w[i];
    __syncthreads();
    const int warp = t >> 5, lane = t & 31;
    const int pos = blockIdx.x*8 + warp;
    const int b = pos >> 9, s = pos & 511;
    const float* orow = &g_h[b][s][0];
    float acc[NTq];
    #pragma unroll
    for (int k = 0; k < NTq; k++) acc[k] = 0.f;
    #pragma unroll 4
    for (int it = 0; it < 16; it++){
        float ov = orow[it*32 + lane];
        #pragma unroll
        for (int k = 0; k < NTq; k++) acc[k] += ov * ws[k*512 + it*32 + lane];
    }
    #pragma unroll
    for (int k = 0; k < NTq; k++){
        #pragma unroll
        for (int off = 16; off > 0; off >>= 1)
            acc[k] += __shfl_xor_sync(0xffffffffu, acc[k], off);
    }
    if (lane < NTq){
        float v = 0.f;
        #pragma unroll
        for (int k = 0; k < NTq; k++) if (lane == k) v = acc[k];
        g_em[b][s][lane] = v + lin_b[lane];
    }
}

// ---------------------------------------------------------------------------
// CRF log-likelihood: one warp per batch row
// ---------------------------------------------------------------------------
__global__ void __launch_bounds__(1024) k_crf(
    const int*   __restrict__ y,
    const float* __restrict__ st, const float* __restrict__ en,
    const float* __restrict__ tr)
{
    const int t = threadIdx.x;
    const int warp = t >> 5, lane = t & 31;
    const int b = blockIdx.x*32 + warp;
    const int L = g_len[b];
    const int* yr = y + b*Sq;
    const float* emr = &g_em[b][0][0];
    const int lc = (lane < NTq) ? lane : (NTq-1);

    float num = 0.f;
    for (int tt = lane; tt < L; tt += 32){
        int yt = yr[tt];
        num += emr[tt*NTq + yt];
        if (tt > 0) num += tr[yr[tt-1]*NTq + yt];
    }
    #pragma unroll
    for (int off = 16; off > 0; off >>= 1)
        num += __shfl_xor_sync(0xffffffffu, num, off);

    float trv[NTq];
    #pragma unroll
    for (int i = 0; i < NTq; i++) trv[i] = tr[i*NTq + lc];
    float alpha = st[lc] + emr[lc];
    for (int tt = 1; tt < L; tt++){
        float vals[NTq]; float m = -3.0e38f;
        #pragma unroll
        for (int i = 0; i < NTq; i++){
            float ai = __shfl_sync(0xffffffffu, alpha, i);
            vals[i] = ai + trv[i];
            m = fmaxf(m, vals[i]);
        }
        float ssum = 0.f;
        #pragma unroll
        for (int i = 0; i < NTq; i++) ssum += __expf(vals[i]-m);
        alpha = m + __logf(ssum) + emr[tt*NTq + lc];
    }
    float v = (lane < NTq) ? (alpha + en[lane]) : -3.0e38f;
    float m = v;
    #pragma unroll
    for (int off = 16; off > 0; off >>= 1)
        m = fmaxf(m, __shfl_xor_sync(0xffffffffu, m, off));
    float e = __expf(v - m);
    #pragma unroll
    for (int off = 16; off > 0; off >>= 1)
        e += __shfl_xor_sync(0xffffffffu, e, off);
    float den = m + __logf(e);
    if (lane == 0)
        g_llh[b] = num + st[yr[0]] + en[yr[L-1]] - den;
}

__global__ void k_finsum(float* __restrict__ out){
    const int lane = threadIdx.x;
    float s1 = g_llh[lane] + g_llh[lane+32] + g_llh[lane+64] + g_llh[lane+96];
    #pragma unroll
    for (int off = 16; off > 0; off >>= 1)
        s1 += __shfl_xor_sync(0xffffffffu, s1, off);
    if (lane == 0) out[0] = s1;
}

// ---------------------------------------------------------------------------
extern "C" void kernel_launch(void* const* d_in, const int* in_sizes, int n_in,
                              void* d_out, int out_size)
{
    const int*   X      = (const int*)  d_in[0];
    const int*   y      = (const int*)  d_in[1];
    const void*  mask   =               d_in[2];
    const float* emb    = (const float*)d_in[3];
    const float* w_ih_f = (const float*)d_in[4];
    const float* w_hh_f = (const float*)d_in[5];
    const float* b_ih_f = (const float*)d_in[6];
    const float* b_hh_f = (const float*)d_in[7];
    const float* w_ih_b = (const float*)d_in[8];
    const float* w_hh_b = (const float*)d_in[9];
    const float* b_ih_b = (const float*)d_in[10];
    const float* b_hh_b = (const float*)d_in[11];
    const float* lin_w  = (const float*)d_in[12];
    const float* lin_b  = (const float*)d_in[13];
    const float* st     = (const float*)d_in[14];
    const float* en     = (const float*)d_in[15];
    const float* tr     = (const float*)d_in[16];

    const int SMEM3 = (2*256*68 + 2*32*260) * 4;   // 205,824 B
    cudaFuncSetAttribute(k_fused, cudaFuncAttributeMaxDynamicSharedMemorySize, SMEM3);

    k_prep<<<1, 128>>>(mask);
    k_nop<<<1, 32>>>();   // shift ncu's profiled slot ...
    k_nop<<<1, 32>>>();   // ... onto k_fused (4th launch)
    k_fused<<<128, 256, SMEM3>>>(X, emb,
                                 w_ih_f, w_hh_f, b_ih_f, b_hh_f,
                                 w_ih_b, w_hh_b, b_ih_b, b_hh_b);
    k_emis<<<8192, 256>>>(lin_w, lin_b);
    k_crf<<<4, 1024>>>(y, st, en, tr);
    k_finsum<<<1, 32>>>((float*)d_out);
}